// round 16
// baseline (speedup 1.0000x reference)
#include <cuda_runtime.h>
#include <cuda_bf16.h>
#include <cstdint>

#define NROI 128
#define FH 38
#define FW 50
#define K1 25088      // 512*7*7
#define DH 4096
#define SP1 8         // 25088/8 = 3136 = 98 k-tiles of 32; grid 256 = one wave
#define SP2 8         // 4096/8  = 512  = 16 k-tiles
#define SP3 64        // 4096/64 = 64   = 2 k-tiles

// ---------------- PDL helpers ----------------
#define GDC_WAIT()   asm volatile("griddepcontrol.wait;" ::: "memory")
#define GDC_LAUNCH() asm volatile("griddepcontrol.launch_dependents;" ::: "memory")

// ---------------- static scratch ----------------
__device__ __align__(16) __nv_bfloat16 g_xh[NROI * K1];
__device__ __align__(16) __nv_bfloat16 g_xl[NROI * K1];
__device__ __align__(16) __nv_bfloat16 g_h1h[NROI * DH];
__device__ __align__(16) __nv_bfloat16 g_h1l[NROI * DH];
__device__ __align__(16) __nv_bfloat16 g_h2h[NROI * DH];
__device__ __align__(16) __nv_bfloat16 g_h2l[NROI * DH];
__device__ __align__(16) float g_acc1[SP1 * NROI * DH];
__device__ __align__(16) float g_acc2[SP2 * NROI * DH];
__device__ __align__(16) float g_acc3[SP3 * NROI * 128];
__device__ __align__(16) float g_Wc[DH * 128];

// ---------------- fp32 -> (hi,lo) bf16 split ----------------
__device__ __forceinline__ __nv_bfloat16 bf_from_bits(unsigned short v) {
    __nv_bfloat16_raw r; r.x = v; return __nv_bfloat16(r);
}
__device__ __forceinline__ void split1(float x, __nv_bfloat16& hi, __nv_bfloat16& lo) {
    uint32_t u = __float_as_uint(x);
    hi = bf_from_bits((unsigned short)(u >> 16));
    float r = x - __uint_as_float(u & 0xFFFF0000u);
    lo = __float2bfloat16(r);
}
__device__ __forceinline__ uint32_t prmt_hi16(uint32_t a, uint32_t b) {
    uint32_t r;
    asm("prmt.b32 %0,%1,%2,0x7632;" : "=r"(r) : "r"(a), "r"(b));
    return r;
}
__device__ __forceinline__ void split2(float a, float b, uint32_t& hi, uint32_t& lo) {
    uint32_t ua = __float_as_uint(a), ub = __float_as_uint(b);
    hi = prmt_hi16(ua, ub);
    float ra = a - __uint_as_float(ua & 0xFFFF0000u);
    float rb = b - __uint_as_float(ub & 0xFFFF0000u);
    lo = prmt_hi16(__float_as_uint(ra), __float_as_uint(rb));
}

// ---------------- ROI adaptive max pool ----------------
__global__ void __launch_bounds__(256) pool_kernel(const float* __restrict__ feats,
                                                   const float* __restrict__ rois) {
    GDC_LAUNCH();   // pack_w is independent: release dependents immediately
    int roi = blockIdx.x;
    int item = blockIdx.y * 256 + threadIdx.x;
    float r0 = __ldg(&rois[roi * 4 + 0]) * 0.0625f;
    float r1 = __ldg(&rois[roi * 4 + 1]) * 0.0625f;
    float r2 = __ldg(&rois[roi * 4 + 2]) * 0.0625f;
    float r3 = __ldg(&rois[roi * 4 + 3]) * 0.0625f;
    int y0 = (int)truncf(r0), x0 = (int)truncf(r1);
    int y2 = (int)ceilf(r2),  x3 = (int)ceilf(r3);
    int Ly = y2 - y0, Lx = x3 - x0;
    int c = item / 49, b = item - c * 49;
    int i = b / 7, j = b - i * 7;
    int rb0 = y0 + (i * Ly) / 7;
    int rb1 = y0 + ((i + 1) * Ly + 6) / 7;
    int cb0 = x0 + (j * Lx) / 7;
    int cb1 = x0 + ((j + 1) * Lx + 6) / 7;
    const float* f = feats + (size_t)c * (FH * FW);
    float m = -1e30f;
    for (int y = rb0; y < rb1; ++y)
        for (int x = cb0; x < cb1; ++x)
            m = fmaxf(m, __ldg(f + y * FW + x));
    __nv_bfloat16 h, l;
    split1(m, h, l);
    g_xh[(size_t)roi * K1 + item] = h;
    g_xl[(size_t)roi * K1 + item] = l;
}

// ---------------- mma helpers ----------------
__device__ __forceinline__ void ldsm4(uint32_t& r0, uint32_t& r1, uint32_t& r2, uint32_t& r3, uint32_t a) {
    asm volatile("ldmatrix.sync.aligned.m8n8.x4.shared.b16 {%0,%1,%2,%3},[%4];\n"
                 : "=r"(r0), "=r"(r1), "=r"(r2), "=r"(r3) : "r"(a));
}
__device__ __forceinline__ void ldsm4t(uint32_t& r0, uint32_t& r1, uint32_t& r2, uint32_t& r3, uint32_t a) {
    asm volatile("ldmatrix.sync.aligned.m8n8.x4.trans.shared.b16 {%0,%1,%2,%3},[%4];\n"
                 : "=r"(r0), "=r"(r1), "=r"(r2), "=r"(r3) : "r"(a));
}
__device__ __forceinline__ void mma16816(float* c, const uint32_t* a, const uint32_t* b) {
    asm volatile("mma.sync.aligned.m16n8k16.row.col.f32.bf16.bf16.f32 "
                 "{%0,%1,%2,%3},{%4,%5,%6,%7},{%8,%9},{%0,%1,%2,%3};\n"
                 : "+f"(c[0]), "+f"(c[1]), "+f"(c[2]), "+f"(c[3])
                 : "r"(a[0]), "r"(a[1]), "r"(a[2]), "r"(a[3]), "r"(b[0]), "r"(b[1]));
}
#define CP_ASYNC16(dst, src) \
    asm volatile("cp.async.ca.shared.global [%0], [%1], 16;\n" :: "r"(dst), "l"(src))
#define CP_COMMIT() asm volatile("cp.async.commit_group;\n")
#define CP_WAIT0()  asm volatile("cp.async.wait_group 0;\n" ::: "memory")

// smem: sA [buf][plane][128*40] bf16, sB [buf][plane][32*136] bf16
#define A_PLANE 5120   // 128*40 elems
#define B_PLANE 4352   // 32*136 elems
#define SMEM_TOTAL (4 * A_PLANE * 2 + 4 * B_PLANE * 2)   // 75776 bytes

// acc-slice[128,128] = A[128,kchunk] * W[kchunk,128]; bf16x3, fp32 accum.
// Frozen R6/R13 schedule: wstore(buf); cp-wait; sync; prefetch(it+1); compute(buf).
__global__ void __launch_bounds__(256)
gemm_bf16x3(const __nv_bfloat16* __restrict__ Ah,
            const __nv_bfloat16* __restrict__ Al, int lda,
            const float* __restrict__ W, int ldw,
            float* __restrict__ acc, int ldN, int kchunk)
{
    GDC_WAIT();   // no-op when launched without PDL (gemm1)
    extern __shared__ char smem_raw[];
    const uint32_t sbase = (uint32_t)__cvta_generic_to_shared(smem_raw);
    const uint32_t sBbase = sbase + 4 * A_PLANE * 2;

    const int tid = threadIdx.x, lane = tid & 31, wid = tid >> 5;
    const int wm = wid & 1, wn = wid >> 1;      // warp tile: 64 x 32
    const int n0 = blockIdx.x * 128;
    const int kbase = blockIdx.y * kchunk;
    const int iters = kchunk / 32;

    float c[4][4][4];
    #pragma unroll
    for (int i = 0; i < 4; i++)
        #pragma unroll
        for (int j = 0; j < 4; j++)
            #pragma unroll
            for (int r = 0; r < 4; r++) c[i][j][r] = 0.f;

    const int ar = tid >> 2, ac = (tid & 3) * 8;   // A: 64 rows/pass, 8 bf16 = 16B
    const int bk = tid >> 5, bn = (tid & 31) * 4;  // W: 8 k-rows/pass, float4

    auto cpasyncA = [&](int it, int buf) {
        const __nv_bfloat16* ph = Ah + (size_t)ar * lda + kbase + it * 32 + ac;
        const __nv_bfloat16* pl = Al + (size_t)ar * lda + kbase + it * 32 + ac;
        uint32_t d0 = sbase + (uint32_t)(((buf * 2 + 0) * A_PLANE + ar * 40 + ac) * 2);
        uint32_t d1 = sbase + (uint32_t)(((buf * 2 + 1) * A_PLANE + ar * 40 + ac) * 2);
        CP_ASYNC16(d0, ph);
        CP_ASYNC16(d0 + 64 * 40 * 2, ph + (size_t)64 * lda);
        CP_ASYNC16(d1, pl);
        CP_ASYNC16(d1 + 64 * 40 * 2, pl + (size_t)64 * lda);
    };

    float4 wv[4];
    auto wload = [&](int it) {
        const float* Wp = W + (size_t)(kbase + it * 32 + bk) * ldw + n0 + bn;
        #pragma unroll
        for (int p = 0; p < 4; p++) wv[p] = *(const float4*)(Wp + (size_t)(8 * p) * ldw);
    };
    auto wstore = [&](int buf) {
        uint32_t bH = sBbase + (uint32_t)((buf * 2 + 0) * B_PLANE * 2);
        uint32_t bL = sBbase + (uint32_t)((buf * 2 + 1) * B_PLANE * 2);
        #pragma unroll
        for (int p = 0; p < 4; p++) {
            uint32_t h0, l0, h1, l1;
            split2(wv[p].x, wv[p].y, h0, l0);
            split2(wv[p].z, wv[p].w, h1, l1);
            uint32_t off = (uint32_t)(((bk + 8 * p) * 136 + bn) * 2);
            asm volatile("st.shared.v2.b32 [%0], {%1,%2};\n" :: "r"(bH + off), "r"(h0), "r"(h1));
            asm volatile("st.shared.v2.b32 [%0], {%1,%2};\n" :: "r"(bL + off), "r"(l0), "r"(l1));
        }
    };

    cpasyncA(0, 0); CP_COMMIT();
    wload(0);

    for (int it = 0; it < iters; ++it) {
        int buf = it & 1;
        wstore(buf);
        CP_WAIT0();
        __syncthreads();
        if (it + 1 < iters) {
            cpasyncA(it + 1, buf ^ 1); CP_COMMIT();
            wload(it + 1);
        }
        // compute on buffer `buf`
        const uint32_t aH = sbase + (uint32_t)((buf * 2 + 0) * A_PLANE * 2);
        const uint32_t aL = sbase + (uint32_t)((buf * 2 + 1) * A_PLANE * 2);
        const uint32_t bH = sBbase + (uint32_t)((buf * 2 + 0) * B_PLANE * 2);
        const uint32_t bL = sBbase + (uint32_t)((buf * 2 + 1) * B_PLANE * 2);
        #pragma unroll
        for (int ks = 0; ks < 32; ks += 16) {
            uint32_t bhf[4][2], blf[4][2];
            {
                int krow = ks + ((lane >> 3) & 1) * 8 + (lane & 7);
                #pragma unroll
                for (int np = 0; np < 2; np++) {
                    int ncol = wn * 32 + np * 16 + (lane >> 4) * 8;
                    uint32_t off = (uint32_t)(krow * 136 + ncol) * 2;
                    ldsm4t(bhf[2*np][0], bhf[2*np][1], bhf[2*np+1][0], bhf[2*np+1][1], bH + off);
                    ldsm4t(blf[2*np][0], blf[2*np][1], blf[2*np+1][0], blf[2*np+1][1], bL + off);
                }
            }
            #pragma unroll
            for (int mb = 0; mb < 4; mb++) {
                int mrow = wm * 64 + mb * 16 + (lane & 15);
                uint32_t aoff = (uint32_t)(mrow * 40 + ks + (lane >> 4) * 8) * 2;
                uint32_t ah[4], al[4];
                ldsm4(ah[0], ah[1], ah[2], ah[3], aH + aoff);
                ldsm4(al[0], al[1], al[2], al[3], aL + aoff);
                #pragma unroll
                for (int nb = 0; nb < 4; nb++) {
                    mma16816(c[mb][nb], ah, bhf[nb]);   // hi*hi
                    mma16816(c[mb][nb], ah, blf[nb]);   // hi*lo
                    mma16816(c[mb][nb], al, bhf[nb]);   // lo*hi
                }
            }
        }
    }

    float* accp = acc + (size_t)blockIdx.y * 128 * ldN;
    #pragma unroll
    for (int mb = 0; mb < 4; mb++)
        #pragma unroll
        for (int nb = 0; nb < 4; nb++) {
            int row = wm * 64 + mb * 16 + (lane >> 2);
            int col = n0 + wn * 32 + nb * 8 + (lane & 3) * 2;
            *(float2*)&accp[(size_t)row * ldN + col]       = make_float2(c[mb][nb][0], c[mb][nb][1]);
            *(float2*)&accp[(size_t)(row + 8) * ldN + col] = make_float2(c[mb][nb][2], c[mb][nb][3]);
        }
    GDC_LAUNCH();   // acc writes done: release dependent reduce
}

// ---------------- split-K reduce + bias + relu -> bf16 hi/lo (unrolled) ----------------
template <int NS>
__global__ void reduce_relu_split_t(const float* __restrict__ acc,
                                    const float* __restrict__ bias,
                                    __nv_bfloat16* __restrict__ oh,
                                    __nv_bfloat16* __restrict__ ol,
                                    int total4, int ldN) {
    GDC_WAIT();
    int i = blockIdx.x * blockDim.x + threadIdx.x;
    if (i < total4) {
        int e = i * 4;
        float4 v[NS];
        #pragma unroll
        for (int sl = 0; sl < NS; ++sl)
            v[sl] = *(const float4*)&acc[(size_t)sl * total4 * 4 + e];
        float4 s = *(const float4*)&bias[e % ldN];
        #pragma unroll
        for (int sl = 0; sl < NS; ++sl) {
            s.x += v[sl].x; s.y += v[sl].y; s.z += v[sl].z; s.w += v[sl].w;
        }
        s.x = fmaxf(s.x, 0.f); s.y = fmaxf(s.y, 0.f);
        s.z = fmaxf(s.z, 0.f); s.w = fmaxf(s.w, 0.f);
        uint32_t h0, l0, h1, l1;
        split2(s.x, s.y, h0, l0);
        split2(s.z, s.w, h1, l1);
        *(uint2*)&oh[e] = make_uint2(h0, h1);
        *(uint2*)&ol[e] = make_uint2(l0, l1);
    }
    GDC_LAUNCH();
}

__global__ void reduce_final(const float* __restrict__ acc,
                             const float* __restrict__ b_loc,
                             const float* __restrict__ b_score,
                             float* __restrict__ out) {
    GDC_WAIT();
    int i = blockIdx.x * blockDim.x + threadIdx.x;
    if (i < 128 * 105) {
        int r = i / 105, col = i - r * 105;
        float s = 0.f;
        #pragma unroll 16
        for (int sl = 0; sl < SP3; ++sl) s += acc[((size_t)sl * 128 + r) * 128 + col];
        if (col < 84) out[r * 84 + col] = s + b_loc[col];
        else          out[128 * 84 + r * 21 + (col - 84)] = s + b_score[col - 84];
    }
}

__global__ void pack_w(const float* __restrict__ Wl, const float* __restrict__ Ws,
                       float* __restrict__ Wc) {
    int i = blockIdx.x * blockDim.x + threadIdx.x;
    if (i >= DH * 128) return;
    int k = i >> 7, c = i & 127;
    float v = 0.f;
    if (c < 84)       v = Wl[k * 84 + c];
    else if (c < 105) v = Ws[k * 21 + (c - 84)];
    Wc[i] = v;
}

// ---------------- PDL launch helper ----------------
template <typename F, typename... Args>
static void launch_pss(F f, dim3 g, dim3 b, size_t smem, Args... args) {
    cudaLaunchConfig_t cfg = {};
    cfg.gridDim = g; cfg.blockDim = b; cfg.dynamicSmemBytes = smem;
    cudaLaunchAttribute at[1];
    at[0].id = cudaLaunchAttributeProgrammaticStreamSerialization;
    at[0].val.programmaticStreamSerializationAllowed = 1;
    cfg.attrs = at; cfg.numAttrs = 1;
    cudaLaunchKernelEx(&cfg, f, args...);
}

// ---------------- launch ----------------
extern "C" void kernel_launch(void* const* d_in, const int* in_sizes, int n_in,
                              void* d_out, int out_size) {
    const float* feats = (const float*)d_in[0];
    const float* rois  = (const float*)d_in[1];
    const float* W1 = (const float*)d_in[2];
    const float* b1 = (const float*)d_in[3];
    const float* W2 = (const float*)d_in[4];
    const float* b2 = (const float*)d_in[5];
    const float* Wl = (const float*)d_in[6];
    const float* bl = (const float*)d_in[7];
    const float* Ws = (const float*)d_in[8];
    const float* bs = (const float*)d_in[9];
    float* out = (float*)d_out;

    __nv_bfloat16 *gxh, *gxl, *g1h, *g1l, *g2h, *g2l;
    float *ga1, *ga2, *ga3, *gwc;
    cudaGetSymbolAddress((void**)&gxh, g_xh);
    cudaGetSymbolAddress((void**)&gxl, g_xl);
    cudaGetSymbolAddress((void**)&g1h, g_h1h);
    cudaGetSymbolAddress((void**)&g1l, g_h1l);
    cudaGetSymbolAddress((void**)&g2h, g_h2h);
    cudaGetSymbolAddress((void**)&g2l, g_h2l);
    cudaGetSymbolAddress((void**)&ga1, g_acc1);
    cudaGetSymbolAddress((void**)&ga2, g_acc2);
    cudaGetSymbolAddress((void**)&ga3, g_acc3);
    cudaGetSymbolAddress((void**)&gwc, g_Wc);

    cudaFuncSetAttribute(gemm_bf16x3, cudaFuncAttributeMaxDynamicSharedMemorySize, SMEM_TOTAL);

    // idx0: pool (plain, releases dependents at start). idx1: pack (PSS: overlaps pool).
    // idx2: GEMM1 (plain anchor — waits for everything).
    pool_kernel<<<dim3(NROI, 98), 256>>>(feats, rois);
    launch_pss(pack_w, dim3(2048), dim3(256), 0, Wl, Ws, gwc);

    gemm_bf16x3<<<dim3(DH / 128, SP1), 256, SMEM_TOTAL>>>(gxh, gxl, K1, W1, DH,
                                                          ga1, DH, K1 / SP1);
    launch_pss(reduce_relu_split_t<SP1>, dim3((NROI * DH / 4 + 255) / 256), dim3(256), 0,
               (const float*)ga1, b1, g1h, g1l, NROI * DH / 4, DH);

    launch_pss(gemm_bf16x3, dim3(DH / 128, SP2), dim3(256), (size_t)SMEM_TOTAL,
               (const __nv_bfloat16*)g1h, (const __nv_bfloat16*)g1l, DH, W2, DH,
               ga2, DH, DH / SP2);
    launch_pss(reduce_relu_split_t<SP2>, dim3((NROI * DH / 4 + 255) / 256), dim3(256), 0,
               (const float*)ga2, b2, g2h, g2l, NROI * DH / 4, DH);

    launch_pss(gemm_bf16x3, dim3(1, SP3), dim3(256), (size_t)SMEM_TOTAL,
               (const __nv_bfloat16*)g2h, (const __nv_bfloat16*)g2l, DH,
               (const float*)gwc, 128, ga3, 128, DH / SP3);
    launch_pss(reduce_final, dim3((128 * 105 + 255) / 256), dim3(256), 0,
               (const float*)ga3, bl, bs, out);
}

// round 17
// speedup vs baseline: 1.1085x; 1.1085x over previous
#include <cuda_runtime.h>
#include <cuda_bf16.h>
#include <cstdint>

#define NROI 128
#define FH 38
#define FW 50
#define K1 25088      // 512*7*7
#define DH 4096
#define SP1 14        // 25088/14 = 1792 = 56 k-tiles of 32  (measured optimum)
#define SP2 8         // 4096/8  = 512  = 16 k-tiles
#define SP3 64        // 4096/64 = 64   = 2 k-tiles

// ---------------- PDL helpers ----------------
#define GDC_WAIT()   asm volatile("griddepcontrol.wait;" ::: "memory")
#define GDC_LAUNCH() asm volatile("griddepcontrol.launch_dependents;" ::: "memory")

// ---------------- static scratch ----------------
__device__ __align__(16) __nv_bfloat16 g_xh[NROI * K1];
__device__ __align__(16) __nv_bfloat16 g_xl[NROI * K1];
__device__ __align__(16) __nv_bfloat16 g_h1h[NROI * DH];
__device__ __align__(16) __nv_bfloat16 g_h1l[NROI * DH];
__device__ __align__(16) __nv_bfloat16 g_h2h[NROI * DH];
__device__ __align__(16) __nv_bfloat16 g_h2l[NROI * DH];
__device__ __align__(16) float g_acc1[SP1 * NROI * DH];
__device__ __align__(16) float g_acc2[SP2 * NROI * DH];
__device__ __align__(16) float g_acc3[SP3 * NROI * 128];
__device__ __align__(16) float g_Wc[DH * 128];

// ---------------- fp32 -> (hi,lo) bf16 split ----------------
__device__ __forceinline__ __nv_bfloat16 bf_from_bits(unsigned short v) {
    __nv_bfloat16_raw r; r.x = v; return __nv_bfloat16(r);
}
__device__ __forceinline__ void split1(float x, __nv_bfloat16& hi, __nv_bfloat16& lo) {
    uint32_t u = __float_as_uint(x);
    hi = bf_from_bits((unsigned short)(u >> 16));
    float r = x - __uint_as_float(u & 0xFFFF0000u);
    lo = __float2bfloat16(r);
}
__device__ __forceinline__ uint32_t prmt_hi16(uint32_t a, uint32_t b) {
    uint32_t r;
    asm("prmt.b32 %0,%1,%2,0x7632;" : "=r"(r) : "r"(a), "r"(b));
    return r;
}
__device__ __forceinline__ void split2(float a, float b, uint32_t& hi, uint32_t& lo) {
    uint32_t ua = __float_as_uint(a), ub = __float_as_uint(b);
    hi = prmt_hi16(ua, ub);
    float ra = a - __uint_as_float(ua & 0xFFFF0000u);
    float rb = b - __uint_as_float(ub & 0xFFFF0000u);
    lo = prmt_hi16(__float_as_uint(ra), __float_as_uint(rb));
}

// ---------------- ROI adaptive max pool ----------------
__global__ void __launch_bounds__(256) pool_kernel(const float* __restrict__ feats,
                                                   const float* __restrict__ rois) {
    GDC_LAUNCH();   // pack_w is independent: release dependents immediately
    int roi = blockIdx.x;
    int item = blockIdx.y * 256 + threadIdx.x;
    float r0 = __ldg(&rois[roi * 4 + 0]) * 0.0625f;
    float r1 = __ldg(&rois[roi * 4 + 1]) * 0.0625f;
    float r2 = __ldg(&rois[roi * 4 + 2]) * 0.0625f;
    float r3 = __ldg(&rois[roi * 4 + 3]) * 0.0625f;
    int y0 = (int)truncf(r0), x0 = (int)truncf(r1);
    int y2 = (int)ceilf(r2),  x3 = (int)ceilf(r3);
    int Ly = y2 - y0, Lx = x3 - x0;
    int c = item / 49, b = item - c * 49;
    int i = b / 7, j = b - i * 7;
    int rb0 = y0 + (i * Ly) / 7;
    int rb1 = y0 + ((i + 1) * Ly + 6) / 7;
    int cb0 = x0 + (j * Lx) / 7;
    int cb1 = x0 + ((j + 1) * Lx + 6) / 7;
    const float* f = feats + (size_t)c * (FH * FW);
    float m = -1e30f;
    for (int y = rb0; y < rb1; ++y)
        for (int x = cb0; x < cb1; ++x)
            m = fmaxf(m, __ldg(f + y * FW + x));
    __nv_bfloat16 h, l;
    split1(m, h, l);
    g_xh[(size_t)roi * K1 + item] = h;
    g_xl[(size_t)roi * K1 + item] = l;
}

// ---------------- mma helpers ----------------
__device__ __forceinline__ void ldsm4(uint32_t& r0, uint32_t& r1, uint32_t& r2, uint32_t& r3, uint32_t a) {
    asm volatile("ldmatrix.sync.aligned.m8n8.x4.shared.b16 {%0,%1,%2,%3},[%4];\n"
                 : "=r"(r0), "=r"(r1), "=r"(r2), "=r"(r3) : "r"(a));
}
__device__ __forceinline__ void ldsm4t(uint32_t& r0, uint32_t& r1, uint32_t& r2, uint32_t& r3, uint32_t a) {
    asm volatile("ldmatrix.sync.aligned.m8n8.x4.trans.shared.b16 {%0,%1,%2,%3},[%4];\n"
                 : "=r"(r0), "=r"(r1), "=r"(r2), "=r"(r3) : "r"(a));
}
__device__ __forceinline__ void mma16816(float* c, const uint32_t* a, const uint32_t* b) {
    asm volatile("mma.sync.aligned.m16n8k16.row.col.f32.bf16.bf16.f32 "
                 "{%0,%1,%2,%3},{%4,%5,%6,%7},{%8,%9},{%0,%1,%2,%3};\n"
                 : "+f"(c[0]), "+f"(c[1]), "+f"(c[2]), "+f"(c[3])
                 : "r"(a[0]), "r"(a[1]), "r"(a[2]), "r"(a[3]), "r"(b[0]), "r"(b[1]));
}
#define CP_ASYNC16(dst, src) \
    asm volatile("cp.async.ca.shared.global [%0], [%1], 16;\n" :: "r"(dst), "l"(src))
#define CP_COMMIT() asm volatile("cp.async.commit_group;\n")
#define CP_WAIT0()  asm volatile("cp.async.wait_group 0;\n" ::: "memory")

// smem: sA [buf][plane][128*40] bf16, sB [buf][plane][32*136] bf16
#define A_PLANE 5120   // 128*40 elems
#define B_PLANE 4352   // 32*136 elems
#define SMEM_TOTAL (4 * A_PLANE * 2 + 4 * B_PLANE * 2)   // 75776 bytes

// acc-slice[128,128] = A[128,kchunk] * W[kchunk,128]; bf16x3, fp32 accum.
// Frozen R6/R13 schedule: wstore(buf); cp-wait; sync; prefetch(it+1); compute(buf).
__global__ void __launch_bounds__(256)
gemm_bf16x3(const __nv_bfloat16* __restrict__ Ah,
            const __nv_bfloat16* __restrict__ Al, int lda,
            const float* __restrict__ W, int ldw,
            float* __restrict__ acc, int ldN, int kchunk)
{
    GDC_WAIT();   // no-op when launched without PDL (gemm1)
    extern __shared__ char smem_raw[];
    const uint32_t sbase = (uint32_t)__cvta_generic_to_shared(smem_raw);
    const uint32_t sBbase = sbase + 4 * A_PLANE * 2;

    const int tid = threadIdx.x, lane = tid & 31, wid = tid >> 5;
    const int wm = wid & 1, wn = wid >> 1;      // warp tile: 64 x 32
    const int n0 = blockIdx.x * 128;
    const int kbase = blockIdx.y * kchunk;
    const int iters = kchunk / 32;

    float c[4][4][4];
    #pragma unroll
    for (int i = 0; i < 4; i++)
        #pragma unroll
        for (int j = 0; j < 4; j++)
            #pragma unroll
            for (int r = 0; r < 4; r++) c[i][j][r] = 0.f;

    const int ar = tid >> 2, ac = (tid & 3) * 8;   // A: 64 rows/pass, 8 bf16 = 16B
    const int bk = tid >> 5, bn = (tid & 31) * 4;  // W: 8 k-rows/pass, float4

    auto cpasyncA = [&](int it, int buf) {
        const __nv_bfloat16* ph = Ah + (size_t)ar * lda + kbase + it * 32 + ac;
        const __nv_bfloat16* pl = Al + (size_t)ar * lda + kbase + it * 32 + ac;
        uint32_t d0 = sbase + (uint32_t)(((buf * 2 + 0) * A_PLANE + ar * 40 + ac) * 2);
        uint32_t d1 = sbase + (uint32_t)(((buf * 2 + 1) * A_PLANE + ar * 40 + ac) * 2);
        CP_ASYNC16(d0, ph);
        CP_ASYNC16(d0 + 64 * 40 * 2, ph + (size_t)64 * lda);
        CP_ASYNC16(d1, pl);
        CP_ASYNC16(d1 + 64 * 40 * 2, pl + (size_t)64 * lda);
    };

    float4 wv[4];
    auto wload = [&](int it) {
        const float* Wp = W + (size_t)(kbase + it * 32 + bk) * ldw + n0 + bn;
        #pragma unroll
        for (int p = 0; p < 4; p++) wv[p] = *(const float4*)(Wp + (size_t)(8 * p) * ldw);
    };
    auto wstore = [&](int buf) {
        uint32_t bH = sBbase + (uint32_t)((buf * 2 + 0) * B_PLANE * 2);
        uint32_t bL = sBbase + (uint32_t)((buf * 2 + 1) * B_PLANE * 2);
        #pragma unroll
        for (int p = 0; p < 4; p++) {
            uint32_t h0, l0, h1, l1;
            split2(wv[p].x, wv[p].y, h0, l0);
            split2(wv[p].z, wv[p].w, h1, l1);
            uint32_t off = (uint32_t)(((bk + 8 * p) * 136 + bn) * 2);
            asm volatile("st.shared.v2.b32 [%0], {%1,%2};\n" :: "r"(bH + off), "r"(h0), "r"(h1));
            asm volatile("st.shared.v2.b32 [%0], {%1,%2};\n" :: "r"(bL + off), "r"(l0), "r"(l1));
        }
    };

    cpasyncA(0, 0); CP_COMMIT();
    wload(0);

    for (int it = 0; it < iters; ++it) {
        int buf = it & 1;
        wstore(buf);
        CP_WAIT0();
        __syncthreads();
        if (it + 1 < iters) {
            cpasyncA(it + 1, buf ^ 1); CP_COMMIT();
            wload(it + 1);
        }
        // compute on buffer `buf`
        const uint32_t aH = sbase + (uint32_t)((buf * 2 + 0) * A_PLANE * 2);
        const uint32_t aL = sbase + (uint32_t)((buf * 2 + 1) * A_PLANE * 2);
        const uint32_t bH = sBbase + (uint32_t)((buf * 2 + 0) * B_PLANE * 2);
        const uint32_t bL = sBbase + (uint32_t)((buf * 2 + 1) * B_PLANE * 2);
        #pragma unroll
        for (int ks = 0; ks < 32; ks += 16) {
            uint32_t bhf[4][2], blf[4][2];
            {
                int krow = ks + ((lane >> 3) & 1) * 8 + (lane & 7);
                #pragma unroll
                for (int np = 0; np < 2; np++) {
                    int ncol = wn * 32 + np * 16 + (lane >> 4) * 8;
                    uint32_t off = (uint32_t)(krow * 136 + ncol) * 2;
                    ldsm4t(bhf[2*np][0], bhf[2*np][1], bhf[2*np+1][0], bhf[2*np+1][1], bH + off);
                    ldsm4t(blf[2*np][0], blf[2*np][1], blf[2*np+1][0], blf[2*np+1][1], bL + off);
                }
            }
            #pragma unroll
            for (int mb = 0; mb < 4; mb++) {
                int mrow = wm * 64 + mb * 16 + (lane & 15);
                uint32_t aoff = (uint32_t)(mrow * 40 + ks + (lane >> 4) * 8) * 2;
                uint32_t ah[4], al[4];
                ldsm4(ah[0], ah[1], ah[2], ah[3], aH + aoff);
                ldsm4(al[0], al[1], al[2], al[3], aL + aoff);
                #pragma unroll
                for (int nb = 0; nb < 4; nb++) {
                    mma16816(c[mb][nb], ah, bhf[nb]);   // hi*hi
                    mma16816(c[mb][nb], ah, blf[nb]);   // hi*lo
                    mma16816(c[mb][nb], al, bhf[nb]);   // lo*hi
                }
            }
        }
    }

    float* accp = acc + (size_t)blockIdx.y * 128 * ldN;
    #pragma unroll
    for (int mb = 0; mb < 4; mb++)
        #pragma unroll
        for (int nb = 0; nb < 4; nb++) {
            int row = wm * 64 + mb * 16 + (lane >> 2);
            int col = n0 + wn * 32 + nb * 8 + (lane & 3) * 2;
            *(float2*)&accp[(size_t)row * ldN + col]       = make_float2(c[mb][nb][0], c[mb][nb][1]);
            *(float2*)&accp[(size_t)(row + 8) * ldN + col] = make_float2(c[mb][nb][2], c[mb][nb][3]);
        }
    GDC_LAUNCH();   // acc writes done: release dependent reduce
}

// ---- split-K reduce + bias + relu -> bf16 hi/lo (float2 granularity, 2x threads) ----
template <int NS>
__global__ void reduce_relu_split_t(const float* __restrict__ acc,
                                    const float* __restrict__ bias,
                                    __nv_bfloat16* __restrict__ oh,
                                    __nv_bfloat16* __restrict__ ol,
                                    int total2, int ldN) {
    GDC_WAIT();
    int i = blockIdx.x * blockDim.x + threadIdx.x;
    if (i < total2) {
        int e = i * 2;
        float2 v[NS];
        #pragma unroll
        for (int sl = 0; sl < NS; ++sl)
            v[sl] = *(const float2*)&acc[(size_t)sl * total2 * 2 + e];
        float2 s = *(const float2*)&bias[e % ldN];
        #pragma unroll
        for (int sl = 0; sl < NS; ++sl) { s.x += v[sl].x; s.y += v[sl].y; }
        s.x = fmaxf(s.x, 0.f); s.y = fmaxf(s.y, 0.f);
        uint32_t h0, l0;
        split2(s.x, s.y, h0, l0);
        *(uint32_t*)&oh[e] = h0;
        *(uint32_t*)&ol[e] = l0;
    }
    GDC_LAUNCH();
}

__global__ void reduce_final(const float* __restrict__ acc,
                             const float* __restrict__ b_loc,
                             const float* __restrict__ b_score,
                             float* __restrict__ out) {
    GDC_WAIT();
    int i = blockIdx.x * blockDim.x + threadIdx.x;
    if (i < 128 * 105) {
        int r = i / 105, col = i - r * 105;
        float s = 0.f;
        #pragma unroll 16
        for (int sl = 0; sl < SP3; ++sl) s += acc[((size_t)sl * 128 + r) * 128 + col];
        if (col < 84) out[r * 84 + col] = s + b_loc[col];
        else          out[128 * 84 + r * 21 + (col - 84)] = s + b_score[col - 84];
    }
}

__global__ void pack_w(const float* __restrict__ Wl, const float* __restrict__ Ws,
                       float* __restrict__ Wc) {
    int i = blockIdx.x * blockDim.x + threadIdx.x;
    if (i >= DH * 128) return;
    int k = i >> 7, c = i & 127;
    float v = 0.f;
    if (c < 84)       v = Wl[k * 84 + c];
    else if (c < 105) v = Ws[k * 21 + (c - 84)];
    Wc[i] = v;
}

// ---------------- PDL launch helper ----------------
template <typename F, typename... Args>
static void launch_pss(F f, dim3 g, dim3 b, size_t smem, Args... args) {
    cudaLaunchConfig_t cfg = {};
    cfg.gridDim = g; cfg.blockDim = b; cfg.dynamicSmemBytes = smem;
    cudaLaunchAttribute at[1];
    at[0].id = cudaLaunchAttributeProgrammaticStreamSerialization;
    at[0].val.programmaticStreamSerializationAllowed = 1;
    cfg.attrs = at; cfg.numAttrs = 1;
    cudaLaunchKernelEx(&cfg, f, args...);
}

// ---------------- launch ----------------
extern "C" void kernel_launch(void* const* d_in, const int* in_sizes, int n_in,
                              void* d_out, int out_size) {
    const float* feats = (const float*)d_in[0];
    const float* rois  = (const float*)d_in[1];
    const float* W1 = (const float*)d_in[2];
    const float* b1 = (const float*)d_in[3];
    const float* W2 = (const float*)d_in[4];
    const float* b2 = (const float*)d_in[5];
    const float* Wl = (const float*)d_in[6];
    const float* bl = (const float*)d_in[7];
    const float* Ws = (const float*)d_in[8];
    const float* bs = (const float*)d_in[9];
    float* out = (float*)d_out;

    __nv_bfloat16 *gxh, *gxl, *g1h, *g1l, *g2h, *g2l;
    float *ga1, *ga2, *ga3, *gwc;
    cudaGetSymbolAddress((void**)&gxh, g_xh);
    cudaGetSymbolAddress((void**)&gxl, g_xl);
    cudaGetSymbolAddress((void**)&g1h, g_h1h);
    cudaGetSymbolAddress((void**)&g1l, g_h1l);
    cudaGetSymbolAddress((void**)&g2h, g_h2h);
    cudaGetSymbolAddress((void**)&g2l, g_h2l);
    cudaGetSymbolAddress((void**)&ga1, g_acc1);
    cudaGetSymbolAddress((void**)&ga2, g_acc2);
    cudaGetSymbolAddress((void**)&ga3, g_acc3);
    cudaGetSymbolAddress((void**)&gwc, g_Wc);

    cudaFuncSetAttribute(gemm_bf16x3, cudaFuncAttributeMaxDynamicSharedMemorySize, SMEM_TOTAL);

    // idx0: pool (plain, releases dependents at start). idx1: pack (PSS: overlaps pool).
    // idx2: GEMM1 (plain anchor — waits for everything).
    pool_kernel<<<dim3(NROI, 98), 256>>>(feats, rois);
    launch_pss(pack_w, dim3(2048), dim3(256), 0, Wl, Ws, gwc);

    gemm_bf16x3<<<dim3(DH / 128, SP1), 256, SMEM_TOTAL>>>(gxh, gxl, K1, W1, DH,
                                                          ga1, DH, K1 / SP1);
    launch_pss(reduce_relu_split_t<SP1>, dim3((NROI * DH / 2 + 255) / 256), dim3(256), 0,
               (const float*)ga1, b1, g1h, g1l, NROI * DH / 2, DH);

    launch_pss(gemm_bf16x3, dim3(DH / 128, SP2), dim3(256), (size_t)SMEM_TOTAL,
               (const __nv_bfloat16*)g1h, (const __nv_bfloat16*)g1l, DH, W2, DH,
               ga2, DH, DH / SP2);
    launch_pss(reduce_relu_split_t<SP2>, dim3((NROI * DH / 2 + 255) / 256), dim3(256), 0,
               (const float*)ga2, b2, g2h, g2l, NROI * DH / 2, DH);

    launch_pss(gemm_bf16x3, dim3(1, SP3), dim3(256), (size_t)SMEM_TOTAL,
               (const __nv_bfloat16*)g2h, (const __nv_bfloat16*)g2l, DH,
               (const float*)gwc, 128, ga3, 128, DH / SP3);
    launch_pss(reduce_final, dim3((128 * 105 + 255) / 256), dim3(256), 0,
               (const float*)ga3, bl, bs, out);
}